// round 4
// baseline (speedup 1.0000x reference)
#include <cuda_runtime.h>
#include <math.h>

#define B_   128
#define S_   512
#define T_   36
#define STARTT 34
#define ENDT   35

// dynamic smem layout (floats):
//  [0, 18432)        exp(feats) for this batch (S*T)
//  [18432, 19728)    raw transitions (36*36)
//  [19728, 19856)    reduction scratch (128)
//  [19856]           gold score
#define EF 0
#define TR 18432
#define RD 19728
#define GD 19856
#define SMEM_FLOATS 19860
#define SMEM_BYTES  (SMEM_FLOATS * 4)

typedef unsigned long long ull;

__device__ float g_partial[B_];
__device__ int   g_count = 0;

__device__ __forceinline__ ull ffma2(ull a, ull b, ull c) {
    ull d;
    asm("fma.rn.f32x2 %0, %1, %2, %3;" : "=l"(d) : "l"(a), "l"(b), "l"(c));
    return d;
}
__device__ __forceinline__ ull fadd2(ull a, ull b) {
    ull d;
    asm("add.rn.f32x2 %0, %1, %2;" : "=l"(d) : "l"(a), "l"(b));
    return d;
}
__device__ __forceinline__ ull pack2(float lo, float hi) {
    ull d;
    asm("mov.b64 %0, {%1, %2};" : "=l"(d) : "f"(lo), "f"(hi));
    return d;
}
__device__ __forceinline__ void unpack2(ull v, float& lo, float& hi) {
    asm("mov.b64 {%0, %1}, %2;" : "=f"(lo), "=f"(hi) : "l"(v));
}

// One forward step entirely in registers. p pairs live in lanes 0-16; all lanes
// gather them via shfl (no smem, no barrier). RENORM: power-of-two rescale.
template <bool RENORM>
__device__ __forceinline__ void crf_step(float2& pc, const ull* __restrict__ EA,
                                         const ull* __restrict__ EB,
                                         float2 ef2, int& Ksum)
{
    const ull pcu = pack2(pc.x, pc.y);
    ull V[17];
    #pragma unroll
    for (int m = 0; m < 17; m++)
        V[m] = __shfl_sync(0xFFFFFFFFu, pcu, m);

    float sc = 1.0f;
    if (RENORM) {
        const unsigned p0 = (unsigned)(V[0] & 0xFFFFFFFFull);
        const int k = (int)((p0 >> 23) & 0xFF) - 127;   // p0>0 finite always
        Ksum += k;
        sc = __int_as_float((unsigned)(127 - k) << 23); // 2^-k
    }

    ull accA[6] = {0, 0, 0, 0, 0, 0};
    ull accB[6] = {0, 0, 0, 0, 0, 0};
    #pragma unroll
    for (int m = 0; m < 17; m++) {
        accA[m % 6] = ffma2(V[m], EA[m], accA[m % 6]);
        accB[m % 6] = ffma2(V[m], EB[m], accB[m % 6]);
    }
    const ull rA = fadd2(fadd2(fadd2(accA[0], accA[1]), fadd2(accA[2], accA[3])),
                         fadd2(accA[4], accA[5]));
    const ull rB = fadd2(fadd2(fadd2(accB[0], accB[1]), fadd2(accB[2], accB[3])),
                         fadd2(accB[4], accB[5]));
    float a0, a1, b0, b1;
    unpack2(rA, a0, a1);
    unpack2(rB, b0, b1);
    if (RENORM) {
        pc.x = (a0 + b1) * (ef2.x * sc);
        pc.y = (a1 + b0) * (ef2.y * sc);
    } else {
        pc.x = (a0 + b1) * ef2.x;
        pc.y = (a1 + b0) * ef2.y;
    }
}

__global__ void __launch_bounds__(128, 1)
crf_kernel(const float* __restrict__ feats,
           const float* __restrict__ transitions,
           const int*   __restrict__ mask,
           const int*   __restrict__ tags,
           float*       __restrict__ out)
{
    extern __shared__ float sh[];
    const int tid  = threadIdx.x;
    const int lane = tid & 31;
    const int wid  = tid >> 5;
    const int b    = blockIdx.x;

    // ---- stage exp(feats[b]) (72KB) + raw transitions into smem, coalesced ----
    {
        const float4* fsrc = (const float4*)(feats + (size_t)b * (S_ * T_));
        float4* fdst = (float4*)(sh + EF);
        #pragma unroll
        for (int i = 0; i < (S_ * T_ / 4) / 128; i++) {   // 36 iters
            float4 v = fsrc[tid + i * 128];
            v.x = __expf(v.x); v.y = __expf(v.y);
            v.z = __expf(v.z); v.w = __expf(v.w);
            fdst[tid + i * 128] = v;
        }
        const float4* tsrc = (const float4*)transitions;
        float4* tdst = (float4*)(sh + TR);
        for (int i = tid; i < (T_ * T_ / 4); i += 128)
            tdst[i] = tsrc[i];
    }

    // ---- sequence length (mask is a contiguous prefix) ----
    int lsum = 0;
    {
        const int* mrow = mask + b * S_;
        #pragma unroll
        for (int i = 0; i < 4; i++) lsum += mrow[tid + i * 128];
    }
    #pragma unroll
    for (int off = 16; off > 0; off >>= 1)
        lsum += __shfl_xor_sync(0xFFFFFFFFu, lsum, off);
    if (lane == 0) ((int*)(sh + RD))[wid] = lsum;
    __syncthreads();
    const int len = ((const int*)(sh + RD))[0] + ((const int*)(sh + RD))[1]
                  + ((const int*)(sh + RD))[2] + ((const int*)(sh + RD))[3];

    float fwd = 0.0f;

    if (wid == 0) {
        // =========== warp 0: forward scan, p in registers, shfl exchange ===========
        const int l  = (lane < 17) ? lane : 16;   // pad lanes duplicate pair 16
        const int j0 = 2 * l, j1 = 2 * l + 1;

        // cross-packed E:  EA[m]=(E[2m][j0],E[2m+1][j1])  EB[m]=(E[2m][j1],E[2m+1][j0])
        ull EA[17], EB[17];
        #pragma unroll
        for (int m = 0; m < 17; m++) {
            const float t00 = __expf(sh[TR + (2 * m)     * T_ + j0]);
            const float t01 = __expf(sh[TR + (2 * m)     * T_ + j1]);
            const float t10 = __expf(sh[TR + (2 * m + 1) * T_ + j0]);
            const float t11 = __expf(sh[TR + (2 * m + 1) * T_ + j1]);
            EA[m] = pack2(t00, t11);
            EB[m] = pack2(t01, t10);
        }

        // init: p_j = exp(feats[0,j]) * exp(tr[START,j])
        float2 pc;
        pc.x = sh[EF + j0] * __expf(sh[TR + STARTT * T_ + j0]);
        pc.y = sh[EF + j1] * __expf(sh[TR + STARTT * T_ + j1]);

        int Ksum = 0;
        int t = 1;
        for (; t + 1 < len; t += 2) {
            const float2 efA = *(const float2*)(sh + EF + t * T_ + j0);
            const float2 efB = *(const float2*)(sh + EF + (t + 1) * T_ + j0);
            crf_step<true >(pc, EA, EB, efA, Ksum);   // renorm on even step
            crf_step<false>(pc, EA, EB, efB, Ksum);   // growth over 2 steps << fp32 range
        }
        if (t < len) {
            const float2 efA = *(const float2*)(sh + EF + t * T_ + j0);
            crf_step<true>(pc, EA, EB, efA, Ksum);
        }

        // forward score: log(sum_j p_j * exp(tr[j][END])) + Ksum*ln2
        const float e0 = __expf(sh[TR + j0 * T_ + ENDT]);
        const float e1 = __expf(sh[TR + j1 * T_ + ENDT]);
        float contrib = (lane < 17) ? (pc.x * e0 + pc.y * e1) : 0.0f;
        #pragma unroll
        for (int off = 16; off > 0; off >>= 1)
            contrib += __shfl_xor_sync(0xFFFFFFFFu, contrib, off);
        fwd = __logf(contrib) + (float)Ksum * 0.6931471805599453f;
    } else {
        // =========== warps 1-3: gold score (concurrent with the scan) ===========
        const int*   trow = tags  + b * S_;
        const float* frow = feats + (size_t)b * (S_ * T_);
        float g = 0.0f;
        for (int t = tid - 32; t < len; t += 96) {
            const int tg = trow[t];
            const int pv = (t == 0) ? STARTT : trow[t - 1];
            g += __ldg(frow + t * T_ + tg) + sh[TR + pv * T_ + tg];
        }
        #pragma unroll
        for (int off = 16; off > 0; off >>= 1)
            g += __shfl_xor_sync(0xFFFFFFFFu, g, off);
        if (lane == 0) sh[RD + wid] = g;
        asm volatile("bar.sync 1, 96;" ::: "memory");
        if (tid == 32) {
            const float endE = sh[TR + trow[len - 1] * T_ + ENDT];
            sh[GD] = sh[RD + 1] + sh[RD + 2] + sh[RD + 3] + endE;
        }
    }

    __syncthreads();
    if (tid == 0) g_partial[b] = fwd - sh[GD];

    // ---- fused finalize: last block reduces all partials (deterministic) ----
    __shared__ int lastflag;
    __threadfence();
    if (tid == 0) lastflag = (atomicAdd(&g_count, 1) == B_ - 1);
    __syncthreads();
    if (lastflag) {
        volatile const float* gp = g_partial;
        sh[RD + tid] = gp[tid];
        __syncthreads();
        #pragma unroll
        for (int off = 64; off > 0; off >>= 1) {
            if (tid < off) sh[RD + tid] += sh[RD + tid + off];
            __syncthreads();
        }
        if (tid == 0) {
            out[0] = sh[RD] * (1.0f / (float)B_);
            g_count = 0;   // reset for next graph replay
        }
    }
}

extern "C" void kernel_launch(void* const* d_in, const int* in_sizes, int n_in,
                              void* d_out, int out_size)
{
    const float* feats = (const float*)d_in[0];
    const float* trans = (const float*)d_in[1];
    const int*   mask  = (const int*)d_in[2];
    const int*   tags  = (const int*)d_in[3];

    cudaFuncSetAttribute((const void*)crf_kernel,
                         cudaFuncAttributeMaxDynamicSharedMemorySize, SMEM_BYTES);
    crf_kernel<<<B_, 128, SMEM_BYTES>>>(feats, trans, mask, tags, (float*)d_out);
}

// round 5
// speedup vs baseline: 1.9251x; 1.9251x over previous
#include <cuda_runtime.h>
#include <math.h>

#define B_   128
#define S_   512
#define T_   36
#define STARTT 34
#define ENDT   35

// dynamic smem layout (floats):
//  [0, 18432)        exp(feats) for this batch (S*T)   (reused as finalize scratch)
//  [18432, 19728)    raw transitions (36*36)
//  [19728, 19824)    fwd p ping-pong: 2 x 48
//  [19824, 19920)    bwd q ping-pong: 2 x 48
//  [19920, 19968)    BV: beta vector at meet point (48)
//  [19968, 20000)    RD scratch: [0..3] len partials, [4..5] gold, [6] gold total, [7] Ksb
#define EF  0
#define TR  18432
#define PF  19728
#define PW  19824
#define BV  19920
#define RD  19968
#define SMEM_FLOATS 20000
#define SMEM_BYTES  (SMEM_FLOATS * 4)

typedef unsigned long long ull;

__device__ float g_partial[B_];
__device__ int   g_count = 0;

__device__ __forceinline__ ull ffma2(ull a, ull b, ull c) {
    ull d;
    asm("fma.rn.f32x2 %0, %1, %2, %3;" : "=l"(d) : "l"(a), "l"(b), "l"(c));
    return d;
}
__device__ __forceinline__ ull fadd2(ull a, ull b) {
    ull d;
    asm("add.rn.f32x2 %0, %1, %2;" : "=l"(d) : "l"(a), "l"(b));
    return d;
}
__device__ __forceinline__ ull pack2(float lo, float hi) {
    ull d;
    asm("mov.b64 %0, {%1, %2};" : "=l"(d) : "f"(lo), "f"(hi));
    return d;
}
__device__ __forceinline__ void unpack2(ull v, float& lo, float& hi) {
    asm("mov.b64 {%0, %1}, %2;" : "=f"(lo), "=f"(hi) : "l"(v));
}

// Shared gather + cross-packed mat-vec body (round-3 proven structure).
// Reads the 34-float vector from sbuf (zero-padded to 48), returns the two
// partial sums for this lane's pair, plus the 2^-k renorm factor from elem 0.
__device__ __forceinline__ void gather_matvec(const float* __restrict__ sbuf,
                                              const ull* __restrict__ Ea,
                                              const ull* __restrict__ Eb,
                                              float& r0, float& r1,
                                              float& sc, int& Ksum)
{
    const ulonglong2* Vp = (const ulonglong2*)sbuf;
    ulonglong2 V[9];
    #pragma unroll
    for (int q = 0; q < 9; q++) V[q] = Vp[q];

    // power-of-two renorm from exponent bits of element 0 (always > 0)
    const unsigned p0 = (unsigned)(V[0].x & 0xFFFFFFFFull);
    int k = (int)((p0 >> 23) & 0xFF) - 127;
    k = max(-120, min(120, k));
    Ksum += k;
    sc = __int_as_float((unsigned)(127 - k) << 23);   // 2^-k

    ull accA[6] = {0, 0, 0, 0, 0, 0};
    ull accB[6] = {0, 0, 0, 0, 0, 0};
    #pragma unroll
    for (int m = 0; m < 17; m++) {
        const ull pm = (m & 1) ? V[m >> 1].y : V[m >> 1].x;
        accA[m % 6] = ffma2(pm, Ea[m], accA[m % 6]);
        accB[m % 6] = ffma2(pm, Eb[m], accB[m % 6]);
    }
    const ull rA = fadd2(fadd2(fadd2(accA[0], accA[1]), fadd2(accA[2], accA[3])),
                         fadd2(accA[4], accA[5]));
    const ull rB = fadd2(fadd2(fadd2(accB[0], accB[1]), fadd2(accB[2], accB[3])),
                         fadd2(accB[4], accB[5]));
    float a0, a1, b0, b1;
    unpack2(rA, a0, a1);
    unpack2(rB, b0, b1);
    r0 = a0 + b1;
    r1 = a1 + b0;
}

__global__ void __launch_bounds__(128, 1)
crf_kernel(const float* __restrict__ feats,
           const float* __restrict__ transitions,
           const int*   __restrict__ mask,
           const int*   __restrict__ tags,
           float*       __restrict__ out)
{
    extern __shared__ float sh[];
    const int tid  = threadIdx.x;
    const int lane = tid & 31;
    const int wid  = tid >> 5;
    const int b    = blockIdx.x;

    // ---- stage exp(feats[b]) (72KB) + raw transitions into smem, coalesced ----
    {
        const float4* fsrc = (const float4*)(feats + (size_t)b * (S_ * T_));
        float4* fdst = (float4*)(sh + EF);
        #pragma unroll
        for (int i = 0; i < (S_ * T_ / 4) / 128; i++) {   // 36 iters
            float4 v = fsrc[tid + i * 128];
            v.x = __expf(v.x); v.y = __expf(v.y);
            v.z = __expf(v.z); v.w = __expf(v.w);
            fdst[tid + i * 128] = v;
        }
        const float4* tsrc = (const float4*)transitions;
        float4* tdst = (float4*)(sh + TR);
        for (int i = tid; i < (T_ * T_ / 4); i += 128)
            tdst[i] = tsrc[i];
        // zero-pad slots 34..47 of all four ping-pong buffers
        if (tid < 14) {
            sh[PF + 34 + tid] = 0.0f;  sh[PF + 48 + 34 + tid] = 0.0f;
            sh[PW + 34 + tid] = 0.0f;  sh[PW + 48 + 34 + tid] = 0.0f;
        }
    }

    // ---- sequence length (mask is a contiguous prefix) ----
    int lsum = 0;
    {
        const int* mrow = mask + b * S_;
        #pragma unroll
        for (int i = 0; i < 4; i++) lsum += mrow[tid + i * 128];
    }
    #pragma unroll
    for (int off = 16; off > 0; off >>= 1)
        lsum += __shfl_xor_sync(0xFFFFFFFFu, lsum, off);
    if (lane == 0) ((int*)(sh + RD))[wid] = lsum;
    __syncthreads();
    const int len = ((const int*)(sh + RD))[0] + ((const int*)(sh + RD))[1]
                  + ((const int*)(sh + RD))[2] + ((const int*)(sh + RD))[3];
    const int nf  = (len - 1) >> 1;     // meet point t = nf

    const int l  = (lane < 17) ? lane : 16;   // pad lanes duplicate pair 16
    const int j0 = 2 * l, j1 = 2 * l + 1;

    float2 pc = make_float2(0.f, 0.f);   // warp0: alpha pair at meet
    int Ksa = 0;

    if (wid == 0) {
        // ===== warp 0: FORWARD chain, t = 1..nf =====
        // cross-packed E (column view): EA[m]=(E[2m][j0],E[2m+1][j1]) EB[m]=(E[2m][j1],E[2m+1][j0])
        ull EA[17], EB[17];
        #pragma unroll
        for (int m = 0; m < 17; m++) {
            const float t00 = __expf(sh[TR + (2 * m)     * T_ + j0]);
            const float t01 = __expf(sh[TR + (2 * m)     * T_ + j1]);
            const float t10 = __expf(sh[TR + (2 * m + 1) * T_ + j0]);
            const float t11 = __expf(sh[TR + (2 * m + 1) * T_ + j1]);
            EA[m] = pack2(t00, t11);
            EB[m] = pack2(t01, t10);
        }
        // init: alpha_0 = exp(f0) * E[START][j]
        pc.x = sh[EF + j0] * __expf(sh[TR + STARTT * T_ + j0]);
        pc.y = sh[EF + j1] * __expf(sh[TR + STARTT * T_ + j1]);
        if (lane < 17) *(float2*)(sh + PF + j0) = pc;
        __syncwarp();

        int buf = 0;
        for (int t = 1; t <= nf; t++) {
            const float2 ef2 = *(const float2*)(sh + EF + t * T_ + j0);
            float r0, r1, sc;
            gather_matvec(sh + PF + buf * 48, EA, EB, r0, r1, sc, Ksa);
            pc.x = r0 * (ef2.x * sc);
            pc.y = r1 * (ef2.y * sc);
            if (lane < 17) *(float2*)(sh + PF + (buf ^ 1) * 48 + j0) = pc;
            __syncwarp();
            buf ^= 1;
        }
        // pc = alpha_nf * 2^-Ksa  (kept in regs for the final dot)
    } else if (wid == 1) {
        // ===== warp 1: BACKWARD chain, t = len-1 .. nf+1 =====
        // row view of E for this lane's state pair (i0=j0, i1=j1):
        //  TA[m]=(E[i0][2m],E[i1][2m+1])  TB[m]=(E[i1][2m],E[i0][2m+1])
        ull TA[17], TB[17];
        #pragma unroll
        for (int m = 0; m < 17; m++) {
            const float t00 = __expf(sh[TR + j0 * T_ + (2 * m)]);
            const float t01 = __expf(sh[TR + j0 * T_ + (2 * m + 1)]);
            const float t10 = __expf(sh[TR + j1 * T_ + (2 * m)]);
            const float t11 = __expf(sh[TR + j1 * T_ + (2 * m + 1)]);
            TA[m] = pack2(t00, t11);
            TB[m] = pack2(t10, t01);
        }
        // init: beta_{len-1}[i] = E[i][END]
        float2 bc;
        bc.x = __expf(sh[TR + j0 * T_ + ENDT]);
        bc.y = __expf(sh[TR + j1 * T_ + ENDT]);

        int Ksb = 0;
        int buf = 0;
        for (int t = len - 1; t > nf; t--) {
            // q_j = ef_t[j] * beta_t[j]
            const float2 ef2 = *(const float2*)(sh + EF + t * T_ + j0);
            float2 qc;
            qc.x = bc.x * ef2.x;
            qc.y = bc.y * ef2.y;
            if (lane < 17) *(float2*)(sh + PW + buf * 48 + j0) = qc;
            __syncwarp();
            float r0, r1, sc;
            gather_matvec(sh + PW + buf * 48, TA, TB, r0, r1, sc, Ksb);
            bc.x = r0 * sc;
            bc.y = r1 * sc;
            buf ^= 1;
        }
        // publish beta_nf and Ksb
        if (lane < 17) *(float2*)(sh + BV + j0) = bc;
        if (lane == 0) ((int*)(sh + RD))[7] = Ksb;
    } else {
        // ===== warps 2-3: gold score (concurrent with both chains) =====
        const int*   trow = tags  + b * S_;
        const float* frow = feats + (size_t)b * (S_ * T_);
        float g = 0.0f;
        for (int t = tid - 64; t < len; t += 64) {
            const int tg = trow[t];
            const int pv = (t == 0) ? STARTT : trow[t - 1];
            g += __ldg(frow + t * T_ + tg) + sh[TR + pv * T_ + tg];
        }
        #pragma unroll
        for (int off = 16; off > 0; off >>= 1)
            g += __shfl_xor_sync(0xFFFFFFFFu, g, off);
        if (lane == 0) sh[RD + 4 + (wid - 2)] = g;
        asm volatile("bar.sync 2, 64;" ::: "memory");
        if (tid == 64) {
            const float endE = sh[TR + trow[len - 1] * T_ + ENDT];
            sh[RD + 6] = sh[RD + 4] + sh[RD + 5] + endE;
        }
    }

    __syncthreads();

    // ---- combine: Z = sum_i alpha_nf[i] * beta_nf[i]  (warp 0) ----
    if (wid == 0) {
        const float2 bv = *(const float2*)(sh + BV + j0);
        float contrib = (lane < 17) ? (pc.x * bv.x + pc.y * bv.y) : 0.0f;
        #pragma unroll
        for (int off = 16; off > 0; off >>= 1)
            contrib += __shfl_xor_sync(0xFFFFFFFFu, contrib, off);
        if (lane == 0) {
            const int Ksb = ((const int*)(sh + RD))[7];
            const float fwd = __logf(contrib)
                            + (float)(Ksa + Ksb) * 0.6931471805599453f;
            g_partial[b] = fwd - sh[RD + 6];
        }
    }

    // ---- fused finalize: last block reduces all partials (deterministic) ----
    __shared__ int lastflag;
    __threadfence();
    if (tid == 0) lastflag = (atomicAdd(&g_count, 1) == B_ - 1);
    __syncthreads();
    if (lastflag) {
        __threadfence();
        volatile const float* gp = g_partial;
        sh[tid] = gp[tid];                   // reuse EF region as scratch
        __syncthreads();
        #pragma unroll
        for (int off = 64; off > 0; off >>= 1) {
            if (tid < off) sh[tid] += sh[tid + off];
            __syncthreads();
        }
        if (tid == 0) {
            out[0] = sh[0] * (1.0f / (float)B_);
            g_count = 0;   // reset for next graph replay
        }
    }
}

extern "C" void kernel_launch(void* const* d_in, const int* in_sizes, int n_in,
                              void* d_out, int out_size)
{
    const float* feats = (const float*)d_in[0];
    const float* trans = (const float*)d_in[1];
    const int*   mask  = (const int*)d_in[2];
    const int*   tags  = (const int*)d_in[3];

    cudaFuncSetAttribute((const void*)crf_kernel,
                         cudaFuncAttributeMaxDynamicSharedMemorySize, SMEM_BYTES);
    crf_kernel<<<B_, 128, SMEM_BYTES>>>(feats, trans, mask, tags, (float*)d_out);
}

// round 6
// speedup vs baseline: 2.3011x; 1.1953x over previous
#include <cuda_runtime.h>
#include <math.h>

#define B_   128
#define S_   512
#define T_   36
#define STARTT 34
#define ENDT   35
#define NTHREADS 192

// dynamic smem layout (floats):
//  [0, 18432)        exp(feats) for this batch (S*T)   (reused as finalize scratch)
//  [18432, 19728)    raw transitions (36*36)
//  [19728, 19824)    fwd p ping-pong: 2 x 48
//  [19824, 19920)    bwd q ping-pong: 2 x 48
//  [19920, 19968)    AV: alpha at meet (48)
//  [19968, 20016)    BV: beta at meet (48)
//  [20016, 20048)    RD scratch: [0..5] len partials, [6..7] gold, [8] gold total,
//                                [9] Ksa, [10] Ksb
#define EF  0
#define TR  18432
#define PF  19728
#define PW  19824
#define AV  19920
#define BV  19968
#define RD  20016
#define SMEM_FLOATS 20048
#define SMEM_BYTES  (SMEM_FLOATS * 4)

typedef unsigned long long ull;

__device__ float g_partial[B_];
__device__ int   g_count = 0;

__device__ __forceinline__ ull ffma2(ull a, ull b, ull c) {
    ull d;
    asm("fma.rn.f32x2 %0, %1, %2, %3;" : "=l"(d) : "l"(a), "l"(b), "l"(c));
    return d;
}
__device__ __forceinline__ ull fadd2(ull a, ull b) {
    ull d;
    asm("add.rn.f32x2 %0, %1, %2;" : "=l"(d) : "l"(a), "l"(b));
    return d;
}
__device__ __forceinline__ ull pack2(float lo, float hi) {
    ull d;
    asm("mov.b64 %0, {%1, %2};" : "=l"(d) : "f"(lo), "f"(hi));
    return d;
}
__device__ __forceinline__ void unpack2(ull v, float& lo, float& hi) {
    asm("mov.b64 {%0, %1}, %2;" : "=f"(lo), "=f"(hi) : "l"(v));
}

// Gather the 34-float vector (zero-padded buffer) and compute one scalar
// dot y = sum_i v_i * Ec_i for this lane's column, plus the 2^-k renorm
// factor derived from element 0 of the vector.
__device__ __forceinline__ float gather_dot(const float* __restrict__ sbuf,
                                            const ull* __restrict__ Ec,
                                            float& sc, int& Ksum)
{
    const ulonglong2* Vp = (const ulonglong2*)sbuf;
    ulonglong2 V[9];
    #pragma unroll
    for (int q = 0; q < 9; q++) V[q] = Vp[q];

    const unsigned p0 = (unsigned)(V[0].x & 0xFFFFFFFFull);
    int k = (int)((p0 >> 23) & 0xFF) - 127;
    k = max(-120, min(120, k));
    Ksum += k;
    sc = __int_as_float((unsigned)(127 - k) << 23);   // 2^-k

    ull acc[4] = {0, 0, 0, 0};
    #pragma unroll
    for (int m = 0; m < 17; m++) {
        const ull pm = (m & 1) ? V[m >> 1].y : V[m >> 1].x;
        acc[m & 3] = ffma2(pm, Ec[m], acc[m & 3]);
    }
    const ull r = fadd2(fadd2(acc[0], acc[1]), fadd2(acc[2], acc[3]));
    float lo, hi;
    unpack2(r, lo, hi);
    return lo + hi;
}

__global__ void __launch_bounds__(NTHREADS, 1)
crf_kernel(const float* __restrict__ feats,
           const float* __restrict__ transitions,
           const int*   __restrict__ mask,
           const int*   __restrict__ tags,
           float*       __restrict__ out)
{
    extern __shared__ float sh[];
    const int tid  = threadIdx.x;
    const int lane = tid & 31;
    const int wid  = tid >> 5;
    const int b    = blockIdx.x;

    // ---- stage exp(feats[b]) (72KB) + raw transitions into smem, coalesced ----
    {
        const float4* fsrc = (const float4*)(feats + (size_t)b * (S_ * T_));
        float4* fdst = (float4*)(sh + EF);
        #pragma unroll
        for (int i = 0; i < (S_ * T_ / 4) / NTHREADS; i++) {   // 24 iters
            float4 v = fsrc[tid + i * NTHREADS];
            v.x = __expf(v.x); v.y = __expf(v.y);
            v.z = __expf(v.z); v.w = __expf(v.w);
            fdst[tid + i * NTHREADS] = v;
        }
        const float4* tsrc = (const float4*)transitions;
        float4* tdst = (float4*)(sh + TR);
        for (int i = tid; i < (T_ * T_ / 4); i += NTHREADS)
            tdst[i] = tsrc[i];
        // zero-pad slots 34..47 of the four ping-pong buffers
        if (tid < 14) {
            sh[PF + 34 + tid] = 0.0f;  sh[PF + 48 + 34 + tid] = 0.0f;
            sh[PW + 34 + tid] = 0.0f;  sh[PW + 48 + 34 + tid] = 0.0f;
        }
    }

    // ---- sequence length (mask is a contiguous prefix) ----
    int lsum = 0;
    {
        const int* mrow = mask + b * S_;
        for (int i = tid; i < S_; i += NTHREADS) lsum += mrow[i];
    }
    #pragma unroll
    for (int off = 16; off > 0; off >>= 1)
        lsum += __shfl_xor_sync(0xFFFFFFFFu, lsum, off);
    if (lane == 0) ((int*)(sh + RD))[wid] = lsum;
    __syncthreads();
    int len = 0;
    #pragma unroll
    for (int i = 0; i < 6; i++) len += ((const int*)(sh + RD))[i];
    const int nf = (len - 1) >> 1;     // meet point t = nf

    // column/state owned by this lane within its chain-half (one scalar per lane)
    const int half = wid & 1;                        // 0 or 1 within a chain
    const int l    = (lane < 17) ? lane : 16;        // pad lanes duplicate col 16
    const int j    = half * 17 + l;                  // 0..33

    if (wid < 2) {
        // ===== chain FWD (warps 0,1): alpha, t = 1..nf =====
        // column-packed E: Ec[m] = (E[2m][j], E[2m+1][j])
        ull Ec[17];
        #pragma unroll
        for (int m = 0; m < 17; m++)
            Ec[m] = pack2(__expf(sh[TR + (2 * m) * T_ + j]),
                          __expf(sh[TR + (2 * m + 1) * T_ + j]));

        // init: alpha_0[j] = exp(f0[j]) * E[START][j]
        float p = sh[EF + j] * __expf(sh[TR + STARTT * T_ + j]);
        if (lane < 17) sh[PF + j] = p;
        asm volatile("bar.sync 1, 64;" ::: "memory");

        int Ksa = 0;
        int buf = 0;
        for (int t = 1; t <= nf; t++) {
            const float eff = sh[EF + t * T_ + j];     // scalar, off-path
            float sc;
            const float y = gather_dot(sh + PF + buf * 48, Ec, sc, Ksa);
            p = y * (eff * sc);
            if (lane < 17) sh[PF + (buf ^ 1) * 48 + j] = p;
            asm volatile("bar.sync 1, 64;" ::: "memory");
            buf ^= 1;
        }
        if (lane < 17) sh[AV + j] = p;                 // alpha_nf
        if (wid == 0 && lane == 0) ((int*)(sh + RD))[9] = Ksa;
    } else if (wid < 4) {
        // ===== chain BWD (warps 2,3): beta, t = len-1 .. nf+1 =====
        // row-packed E for own state i=j: Er[m] = (E[j][2m], E[j][2m+1])
        ull Er[17];
        #pragma unroll
        for (int m = 0; m < 17; m++)
            Er[m] = pack2(__expf(sh[TR + j * T_ + (2 * m)]),
                          __expf(sh[TR + j * T_ + (2 * m + 1)]));

        // init: beta_{len-1}[i] = E[i][END]
        float bc = __expf(sh[TR + j * T_ + ENDT]);

        int Ksb = 0;
        int buf = 0;
        for (int t = len - 1; t > nf; t--) {
            const float q = bc * sh[EF + t * T_ + j];  // q_i = ef_t[i] * beta_t[i]
            if (lane < 17) sh[PW + buf * 48 + j] = q;
            asm volatile("bar.sync 2, 64;" ::: "memory");
            float sc;
            const float y = gather_dot(sh + PW + buf * 48, Er, sc, Ksb);
            bc = y * sc;
            buf ^= 1;
        }
        if (lane < 17) sh[BV + j] = bc;                // beta_nf
        if (wid == 2 && lane == 0) ((int*)(sh + RD))[10] = Ksb;
    } else {
        // ===== warps 4,5: gold score (concurrent with both chains) =====
        const int*   trow = tags  + b * S_;
        const float* frow = feats + (size_t)b * (S_ * T_);
        float g = 0.0f;
        for (int t = tid - 128; t < len; t += 64) {
            const int tg = trow[t];
            const int pv = (t == 0) ? STARTT : trow[t - 1];
            g += __ldg(frow + t * T_ + tg) + sh[TR + pv * T_ + tg];
        }
        #pragma unroll
        for (int off = 16; off > 0; off >>= 1)
            g += __shfl_xor_sync(0xFFFFFFFFu, g, off);
        if (lane == 0) sh[RD + 6 + (wid - 4)] = g;
        asm volatile("bar.sync 3, 64;" ::: "memory");
        if (tid == 128) {
            const float endE = sh[TR + trow[len - 1] * T_ + ENDT];
            sh[RD + 8] = sh[RD + 6] + sh[RD + 7] + endE;
        }
    }

    __syncthreads();

    // ---- combine: Z = sum_i alpha_nf[i] * beta_nf[i]  (warp 0) ----
    if (wid == 0) {
        const int j0 = 2 * l;
        const float2 av = *(const float2*)(sh + AV + j0);
        const float2 bv = *(const float2*)(sh + BV + j0);
        float contrib = (lane < 17) ? (av.x * bv.x + av.y * bv.y) : 0.0f;
        #pragma unroll
        for (int off = 16; off > 0; off >>= 1)
            contrib += __shfl_xor_sync(0xFFFFFFFFu, contrib, off);
        if (lane == 0) {
            const int Ks = ((const int*)(sh + RD))[9] + ((const int*)(sh + RD))[10];
            const float fwd = __logf(contrib) + (float)Ks * 0.6931471805599453f;
            g_partial[b] = fwd - sh[RD + 8];
        }
    }

    // ---- fused finalize: last block reduces all partials (deterministic) ----
    __shared__ int lastflag;
    __threadfence();
    if (tid == 0) lastflag = (atomicAdd(&g_count, 1) == B_ - 1);
    __syncthreads();
    if (lastflag) {
        __threadfence();
        volatile const float* gp = g_partial;
        if (tid < B_) sh[tid] = gp[tid];      // reuse EF region as scratch
        __syncthreads();
        #pragma unroll
        for (int off = 64; off > 0; off >>= 1) {
            if (tid < off) sh[tid] += sh[tid + off];
            __syncthreads();
        }
        if (tid == 0) {
            out[0] = sh[0] * (1.0f / (float)B_);
            g_count = 0;   // reset for next graph replay
        }
    }
}

extern "C" void kernel_launch(void* const* d_in, const int* in_sizes, int n_in,
                              void* d_out, int out_size)
{
    const float* feats = (const float*)d_in[0];
    const float* trans = (const float*)d_in[1];
    const int*   mask  = (const int*)d_in[2];
    const int*   tags  = (const int*)d_in[3];

    cudaFuncSetAttribute((const void*)crf_kernel,
                         cudaFuncAttributeMaxDynamicSharedMemorySize, SMEM_BYTES);
    crf_kernel<<<B_, NTHREADS, SMEM_BYTES>>>(feats, trans, mask, tags, (float*)d_out);
}

// round 7
// speedup vs baseline: 2.4803x; 1.0779x over previous
#include <cuda_runtime.h>
#include <math.h>

#define B_   128
#define S_   512
#define T_   36
#define STARTT 34
#define ENDT   35
#define NTHREADS 192

// dynamic smem layout (floats):
//  [0, 18432)        exp(feats) for this batch (S*T)   (reused as finalize scratch)
//  [18432, 19728)    raw transitions (36*36)
//  [19728, 19824)    fwd ping-pong: 2 x 48  (each buffer: half0 @ +0, half1 @ +24)
//  [19824, 19920)    bwd ping-pong: 2 x 48
//  [19920, 19968)    AV: alpha at meet
//  [19968, 20016)    BV: beta at meet
//  [20016, 20048)    RD: [0..5] len partials, [6..7] gold, [8] gold total, [9] Ksa, [10] Ksb
#define EF  0
#define TR  18432
#define PF  19728
#define PW  19824
#define AV  19920
#define BV  19968
#define RD  20016
#define SMEM_FLOATS 20048
#define SMEM_BYTES  (SMEM_FLOATS * 4)

typedef unsigned long long ull;

__device__ float g_partial[B_];
__device__ int   g_count = 0;

__device__ __forceinline__ ull ffma2(ull a, ull b, ull c) {
    ull d;
    asm("fma.rn.f32x2 %0, %1, %2, %3;" : "=l"(d) : "l"(a), "l"(b), "l"(c));
    return d;
}
__device__ __forceinline__ ull fadd2(ull a, ull b) {
    ull d;
    asm("add.rn.f32x2 %0, %1, %2;" : "=l"(d) : "l"(a), "l"(b));
    return d;
}
__device__ __forceinline__ ull pack2(float lo, float hi) {
    ull d;
    asm("mov.b64 %0, {%1, %2};" : "=l"(d) : "f"(lo), "f"(hi));
    return d;
}
__device__ __forceinline__ void unpack2(ull v, float& lo, float& hi) {
    asm("mov.b64 {%0, %1}, %2;" : "=f"(lo), "=f"(hi) : "l"(v));
}
__device__ __forceinline__ void bar_arrive64(int id) {
    asm volatile("bar.arrive %0, 64;" :: "r"(id) : "memory");
}
__device__ __forceinline__ void bar_sync64(int id) {
    asm volatile("bar.sync %0, 64;" :: "r"(id) : "memory");
}

// Partial dot over one 17-value half at hb: 16 values as 8 packed pairs + 1 scalar.
// Accumulates into acc0/acc1 (packed) and sS (scalar); returns first u64 (renorm).
__device__ __forceinline__ void half_fma(const float* __restrict__ hb,
                                         const ull* __restrict__ E8, float eS,
                                         ull& acc0, ull& acc1, float& sS, ull& first)
{
    const ulonglong2* W = (const ulonglong2*)hb;
    const ulonglong2 w0 = W[0], w1 = W[1], w2 = W[2], w3 = W[3];
    acc0 = ffma2(w0.x, E8[0], acc0);  acc1 = ffma2(w0.y, E8[1], acc1);
    acc0 = ffma2(w1.x, E8[2], acc0);  acc1 = ffma2(w1.y, E8[3], acc1);
    acc0 = ffma2(w2.x, E8[4], acc0);  acc1 = ffma2(w2.y, E8[5], acc1);
    acc0 = ffma2(w3.x, E8[6], acc0);  acc1 = ffma2(w3.y, E8[7], acc1);
    sS = fmaf(hb[16], eS, sS);
    first = w0.x;
}

__global__ void __launch_bounds__(NTHREADS, 1)
crf_kernel(const float* __restrict__ feats,
           const float* __restrict__ transitions,
           const int*   __restrict__ mask,
           const int*   __restrict__ tags,
           float*       __restrict__ out)
{
    extern __shared__ float sh[];
    const int tid  = threadIdx.x;
    const int lane = tid & 31;
    const int wid  = tid >> 5;
    const int b    = blockIdx.x;

    // ---- stage exp(feats[b]) (72KB) + raw transitions into smem, coalesced ----
    {
        const float4* fsrc = (const float4*)(feats + (size_t)b * (S_ * T_));
        float4* fdst = (float4*)(sh + EF);
        #pragma unroll
        for (int i = 0; i < (S_ * T_ / 4) / NTHREADS; i++) {   // 24 iters
            float4 v = fsrc[tid + i * NTHREADS];
            v.x = __expf(v.x); v.y = __expf(v.y);
            v.z = __expf(v.z); v.w = __expf(v.w);
            fdst[tid + i * NTHREADS] = v;
        }
        const float4* tsrc = (const float4*)transitions;
        float4* tdst = (float4*)(sh + TR);
        for (int i = tid; i < (T_ * T_ / 4); i += NTHREADS)
            tdst[i] = tsrc[i];
    }

    // ---- sequence length (mask is a contiguous prefix) ----
    int lsum = 0;
    {
        const int* mrow = mask + b * S_;
        for (int i = tid; i < S_; i += NTHREADS) lsum += mrow[i];
    }
    #pragma unroll
    for (int off = 16; off > 0; off >>= 1)
        lsum += __shfl_xor_sync(0xFFFFFFFFu, lsum, off);
    if (lane == 0) ((int*)(sh + RD))[wid] = lsum;
    __syncthreads();
    int len = 0;
    #pragma unroll
    for (int i = 0; i < 6; i++) len += ((const int*)(sh + RD))[i];
    const int nf = (len - 1) >> 1;     // meet point t = nf

    const int half = wid & 1;                      // warp's half within its chain
    const int l    = (lane < 17) ? lane : 16;      // pad lanes duplicate col 16
    const int j    = half * 17 + l;                // this lane's column/state, 0..33

    if (wid < 2) {
        // ===== FWD chain (warps 0,1): alpha, t = 1..nf =====
        // column packs split by i-half:
        //  E0[m]=(E[2m][j],E[2m+1][j]) m=0..7 (i=0..15), e16=E[16][j]
        //  E1[m]=(E[17+2m][j],E[18+2m][j])      (i=17..32), e33=E[33][j]
        ull E0[8], E1[8];
        #pragma unroll
        for (int m = 0; m < 8; m++) {
            E0[m] = pack2(__expf(sh[TR + (2 * m) * T_ + j]),
                          __expf(sh[TR + (2 * m + 1) * T_ + j]));
            E1[m] = pack2(__expf(sh[TR + (17 + 2 * m) * T_ + j]),
                          __expf(sh[TR + (18 + 2 * m) * T_ + j]));
        }
        const float e16 = __expf(sh[TR + 16 * T_ + j]);
        const float e33 = __expf(sh[TR + 33 * T_ + j]);
        const ull*  Eown = half ? E1 : E0;
        const ull*  Eoth = half ? E0 : E1;
        const float eOwn = half ? e33 : e16;
        const float eOth = half ? e16 : e33;
        const int   ownOff = half * 24, othOff = 24 - half * 24;
        const int   myArr = 1 + half, mySyn = 2 - half;   // bars 1,2

        float p = sh[EF + j] * __expf(sh[TR + STARTT * T_ + j]);
        int Ks = 0, buf = 0;
        float* pb = sh + PF;
        for (int t = 1; t <= nf; t++) {
            if (lane < 17) pb[buf * 48 + ownOff + lane] = p;
            bar_arrive64(myArr);                 // non-blocking: my half published
            __syncwarp();
            const float eff = sh[EF + t * T_ + j];
            ull a0 = 0, a1 = 0; float sOwn = 0.0f; ull f0own;
            half_fma(pb + buf * 48 + ownOff, Eown, eOwn, a0, a1, sOwn, f0own);
            bar_sync64(mySyn);                   // wait peer's half (work hidden above)
            ull b0 = 0, b1 = 0; float sOth = 0.0f; ull f0oth;
            half_fma(pb + buf * 48 + othOff, Eoth, eOth, b0, b1, sOth, f0oth);

            const ull h0 = half ? f0oth : f0own;          // contains v[0]
            const unsigned p0 = (unsigned)(h0 & 0xFFFFFFFFull);
            const int k = (int)((p0 >> 23) & 0xFF) - 127;
            Ks += k;
            const float sc = __int_as_float((unsigned)(127 - k) << 23);  // 2^-k

            const ull r = fadd2(fadd2(a0, b0), fadd2(a1, b1));
            float lo, hi; unpack2(r, lo, hi);
            p = ((lo + hi) + (sOwn + sOth)) * (eff * sc);
            buf ^= 1;
        }
        if (lane < 17) sh[AV + j] = p;                    // alpha_nf
        if (half == 0 && lane == 0) ((int*)(sh + RD))[9] = Ks;
    } else if (wid < 4) {
        // ===== BWD chain (warps 2,3): beta, t = len-1 .. nf+1 =====
        // row packs for own state i=j, split by k-half:
        //  R0[m]=(E[j][2m],E[j][2m+1]) (k=0..15), r16=E[j][16]
        //  R1[m]=(E[j][17+2m],E[j][18+2m]) (k=17..32), r33=E[j][33]
        ull R0[8], R1[8];
        #pragma unroll
        for (int m = 0; m < 8; m++) {
            R0[m] = pack2(__expf(sh[TR + j * T_ + (2 * m)]),
                          __expf(sh[TR + j * T_ + (2 * m + 1)]));
            R1[m] = pack2(__expf(sh[TR + j * T_ + (17 + 2 * m)]),
                          __expf(sh[TR + j * T_ + (18 + 2 * m)]));
        }
        const float r16 = __expf(sh[TR + j * T_ + 16]);
        const float r33 = __expf(sh[TR + j * T_ + 33]);
        const ull*  Rown = half ? R1 : R0;
        const ull*  Roth = half ? R0 : R1;
        const float rOwn = half ? r33 : r16;
        const float rOth = half ? r16 : r33;
        const int   ownOff = half * 24, othOff = 24 - half * 24;
        const int   myArr = 3 + half, mySyn = 4 - half;   // bars 3,4

        float bc = __expf(sh[TR + j * T_ + ENDT]);        // beta_{len-1}
        int Ks = 0, buf = 0;
        float* wb = sh + PW;
        for (int t = len - 1; t > nf; t--) {
            const float q = bc * sh[EF + t * T_ + j];     // q_i = ef_t[i]*beta_t[i]
            if (lane < 17) wb[buf * 48 + ownOff + lane] = q;
            bar_arrive64(myArr);
            __syncwarp();
            ull a0 = 0, a1 = 0; float sOwn = 0.0f; ull f0own;
            half_fma(wb + buf * 48 + ownOff, Rown, rOwn, a0, a1, sOwn, f0own);
            bar_sync64(mySyn);
            ull b0 = 0, b1 = 0; float sOth = 0.0f; ull f0oth;
            half_fma(wb + buf * 48 + othOff, Roth, rOth, b0, b1, sOth, f0oth);

            const ull h0 = half ? f0oth : f0own;
            const unsigned p0 = (unsigned)(h0 & 0xFFFFFFFFull);
            const int k = (int)((p0 >> 23) & 0xFF) - 127;
            Ks += k;
            const float sc = __int_as_float((unsigned)(127 - k) << 23);

            const ull r = fadd2(fadd2(a0, b0), fadd2(a1, b1));
            float lo, hi; unpack2(r, lo, hi);
            bc = ((lo + hi) + (sOwn + sOth)) * sc;
            buf ^= 1;
        }
        if (lane < 17) sh[BV + j] = bc;                   // beta_nf
        if (half == 0 && lane == 0) ((int*)(sh + RD))[10] = Ks;
    } else {
        // ===== warps 4,5: gold score (concurrent with both chains) =====
        const int*   trow = tags  + b * S_;
        const float* frow = feats + (size_t)b * (S_ * T_);
        float g = 0.0f;
        for (int t = tid - 128; t < len; t += 64) {
            const int tg = trow[t];
            const int pv = (t == 0) ? STARTT : trow[t - 1];
            g += __ldg(frow + t * T_ + tg) + sh[TR + pv * T_ + tg];
        }
        #pragma unroll
        for (int off = 16; off > 0; off >>= 1)
            g += __shfl_xor_sync(0xFFFFFFFFu, g, off);
        if (lane == 0) sh[RD + 6 + (wid - 4)] = g;
        asm volatile("bar.sync 5, 64;" ::: "memory");
        if (tid == 128) {
            const float endE = sh[TR + trow[len - 1] * T_ + ENDT];
            sh[RD + 8] = sh[RD + 6] + sh[RD + 7] + endE;
        }
    }

    __syncthreads();

    // ---- combine: Z = sum_i alpha_nf[i] * beta_nf[i]  (warp 0) ----
    if (wid == 0) {
        const int j0 = 2 * l;
        const float2 av = *(const float2*)(sh + AV + j0);
        const float2 bv = *(const float2*)(sh + BV + j0);
        float contrib = (lane < 17) ? (av.x * bv.x + av.y * bv.y) : 0.0f;
        #pragma unroll
        for (int off = 16; off > 0; off >>= 1)
            contrib += __shfl_xor_sync(0xFFFFFFFFu, contrib, off);
        if (lane == 0) {
            const int Ks = ((const int*)(sh + RD))[9] + ((const int*)(sh + RD))[10];
            const float fwd = __logf(contrib) + (float)Ks * 0.6931471805599453f;
            g_partial[b] = fwd - sh[RD + 8];
        }
    }

    // ---- fused finalize: last block reduces all partials (deterministic) ----
    __shared__ int lastflag;
    __threadfence();
    if (tid == 0) lastflag = (atomicAdd(&g_count, 1) == B_ - 1);
    __syncthreads();
    if (lastflag) {
        __threadfence();
        volatile const float* gp = g_partial;
        if (tid < B_) sh[tid] = gp[tid];      // reuse EF region as scratch
        __syncthreads();
        #pragma unroll
        for (int off = 64; off > 0; off >>= 1) {
            if (tid < off) sh[tid] += sh[tid + off];
            __syncthreads();
        }
        if (tid == 0) {
            out[0] = sh[0] * (1.0f / (float)B_);
            g_count = 0;   // reset for next graph replay
        }
    }
}

extern "C" void kernel_launch(void* const* d_in, const int* in_sizes, int n_in,
                              void* d_out, int out_size)
{
    const float* feats = (const float*)d_in[0];
    const float* trans = (const float*)d_in[1];
    const int*   mask  = (const int*)d_in[2];
    const int*   tags  = (const int*)d_in[3];

    cudaFuncSetAttribute((const void*)crf_kernel,
                         cudaFuncAttributeMaxDynamicSharedMemorySize, SMEM_BYTES);
    crf_kernel<<<B_, NTHREADS, SMEM_BYTES>>>(feats, trans, mask, tags, (float*)d_out);
}